// round 8
// baseline (speedup 1.0000x reference)
#include <cuda_runtime.h>
#include <math.h>

#define NN 100000
#define EE 1600000
#define HH 128
#define CC 64
#define KK 10

typedef unsigned long long u64;

#define GATHER_BLOCKS (NN / 8)   // 12500 gather blocks, 8 nodes each (warp/node)
#define STATS_BLOCKS  (NN / 8)   // 12500 stats blocks

// ---------------- device scratch (allocation-free workaround) ----------------
__device__ __align__(16) float g_featA[NN * HH];
__device__ __align__(16) float g_featB[NN * HH];
__device__ int   g_deg[NN];
__device__ float g_norm[NN];
__device__ float g_invdeg[NN];
__device__ int   g_scan[NN];
__device__ int   g_bsum[128];
__device__ int   g_rowstart[NN + 1];
__device__ int   g_rowcur[NN];
__device__ int   g_csr[EE];
__device__ int   g_pred[NN];
__device__ float g_f1[NN];
__device__ float g_f2[NN];
__device__ float g_z[NN];
__device__ float g_partials[STATS_BLOCKS * 4];
__device__ float g_ln[4];

// ---------------- packed fp32x2 helpers ----------------
__device__ __forceinline__ u64 ffma2(u64 a, u64 b, u64 c) {
    u64 d;
    asm("fma.rn.f32x2 %0, %1, %2, %3;" : "=l"(d) : "l"(a), "l"(b), "l"(c));
    return d;
}
__device__ __forceinline__ u64 pk(float x, float y) {
    u64 d;
    asm("mov.b64 %0, {%1, %2};" : "=l"(d) : "f"(x), "f"(y));
    return d;
}
__device__ __forceinline__ float2 upk(u64 v) {
    float2 r;
    asm("mov.b64 {%0, %1}, %2;" : "=f"(r.x), "=f"(r.y) : "l"(v));
    return r;
}

// ---------------- setup kernels ----------------
__global__ void k_zero() {
    int i = blockIdx.x * blockDim.x + threadIdx.x;
    if (i < NN) { g_deg[i] = 0; g_rowcur[i] = 0; }
}

__global__ void k_deg(const int* __restrict__ dst) {
    int e = blockIdx.x * blockDim.x + threadIdx.x;
    if (e < EE) atomicAdd(&g_deg[dst[e]], 1);
}

__global__ void k_norm() {
    int i = blockIdx.x * blockDim.x + threadIdx.x;
    if (i < NN) {
        int d = g_deg[i];
        float dc = (d > 0) ? (float)d : 1.0f;
        g_norm[i] = rsqrtf(dc);
        g_invdeg[i] = 1.0f / dc;
    }
}

__global__ void k_scan1() {
    __shared__ int sh[1024];
    int tid = threadIdx.x;
    int i = blockIdx.x * 1024 + tid;
    int v = (i < NN) ? g_deg[i] : 0;
    sh[tid] = v;
    __syncthreads();
    for (int off = 1; off < 1024; off <<= 1) {
        int t = (tid >= off) ? sh[tid - off] : 0;
        __syncthreads();
        sh[tid] += t;
        __syncthreads();
    }
    if (i < NN) g_scan[i] = sh[tid];
    if (tid == 1023) g_bsum[blockIdx.x] = sh[1023];
}

__global__ void k_scan2(int nb) {
    int run = 0;
    for (int b = 0; b < nb; b++) { int t = g_bsum[b]; g_bsum[b] = run; run += t; }
}

__global__ void k_scan3() {
    int i = blockIdx.x * blockDim.x + threadIdx.x;
    if (i < NN) g_rowstart[i] = g_scan[i] - g_deg[i] + g_bsum[i >> 10];
    if (i == 0) g_rowstart[NN] = EE;
}

__global__ void k_csrfill(const int* __restrict__ src, const int* __restrict__ dst) {
    int e = blockIdx.x * blockDim.x + threadIdx.x;
    if (e < EE) {
        int d = dst[e];
        int pos = g_rowstart[d] + atomicAdd(&g_rowcur[d], 1);
        g_csr[pos] = src[e];
    }
}

// feat(0) = feat_in * norm -> g_featA
__global__ void k_init(const float* __restrict__ fin) {
    int i = blockIdx.x * blockDim.x + threadIdx.x;
    if (i < NN * (HH / 4)) {
        int n = i >> 5;
        float nm = g_norm[n];
        float4 v = ((const float4*)fin)[i];
        v.x *= nm; v.y *= nm; v.z *= nm; v.w *= nm;
        ((float4*)g_featA)[i] = v;
    }
}

// ---------------- per-iteration kernels ----------------
// Buffer convention: feat(i) lives in sb(i) = (i&1) ? g_featB : g_featA.
// statsgather(i) writes raw agg into sb(i+1); gemm_combine(i+1) turns that
// in-place into feat(i+1) while computing pred(i+1).

// iteration 0: argmax over the input logits
__global__ void k_argmax0(const float* __restrict__ logits) {
    int n = (blockIdx.x * blockDim.x + threadIdx.x) >> 5;
    int lane = threadIdx.x & 31;
    if (n >= NN) return;
    const float* row = logits + (size_t)n * CC;
    float v0 = row[lane], v1 = row[lane + 32];
    float bv; int bc;
    if (v1 > v0) { bv = v1; bc = lane + 32; } else { bv = v0; bc = lane; }
    #pragma unroll
    for (int off = 16; off; off >>= 1) {
        float ov = __shfl_down_sync(0xffffffffu, bv, off);
        int   oc = __shfl_down_sync(0xffffffffu, bc, off);
        if (ov > bv || (ov == bv && oc < bc)) { bv = ov; bc = oc; }
    }
    if (lane == 0) g_pred[n] = bc;
}

// mega-kernel: blocks [0,GATHER_BLOCKS) do the raw SpMM gather
// (agg[n] = sum feat(i)[src]) into the opposite buffer; blocks
// [GATHER_BLOCKS, +STATS_BLOCKS) compute f1/f2 + LN partials.
// 256 threads, warp-per-node, 8 nodes/block. NN % 8 == 0.
__global__ void k_statsgather(int cur) {
    const float* __restrict__ Fs = cur ? g_featB : g_featA;
    float* __restrict__ Fd = cur ? g_featA : g_featB;
    int tid = threadIdx.x, w = tid >> 5, lane = tid & 31;

    if (blockIdx.x < GATHER_BLOCKS) {
        int n = blockIdx.x * 8 + w;
        int rs = g_rowstart[n], re = g_rowstart[n + 1];
        float4 acc = make_float4(0.f, 0.f, 0.f, 0.f);
        int idx = rs;
        for (; idx + 4 <= re; idx += 4) {
            int s0 = g_csr[idx], s1 = g_csr[idx + 1], s2 = g_csr[idx + 2], s3 = g_csr[idx + 3];
            float4 v0 = __ldg((const float4*)(Fs + (size_t)s0 * HH) + lane);
            float4 v1 = __ldg((const float4*)(Fs + (size_t)s1 * HH) + lane);
            float4 v2 = __ldg((const float4*)(Fs + (size_t)s2 * HH) + lane);
            float4 v3 = __ldg((const float4*)(Fs + (size_t)s3 * HH) + lane);
            acc.x += (v0.x + v1.x) + (v2.x + v3.x);
            acc.y += (v0.y + v1.y) + (v2.y + v3.y);
            acc.z += (v0.z + v1.z) + (v2.z + v3.z);
            acc.w += (v0.w + v1.w) + (v2.w + v3.w);
        }
        for (; idx < re; idx++) {
            int s = g_csr[idx];
            float4 v = __ldg((const float4*)(Fs + (size_t)s * HH) + lane);
            acc.x += v.x; acc.y += v.y; acc.z += v.z; acc.w += v.w;
        }
        ((float4*)(Fd + (size_t)n * HH))[lane] = acc;
    } else {
        __shared__ int hist[8][CC];
        __shared__ float4 red[8];
        int bs = blockIdx.x - GATHER_BLOCKS;
        int n = bs * 8 + w;
        hist[w][lane] = 0; hist[w][lane + 32] = 0;
        __syncwarp();
        int pd = g_pred[n];
        int rs = g_rowstart[n], re = g_rowstart[n + 1];
        int eq = 0;
        for (int idx = rs + lane; idx < re; idx += 32) {
            int ps = g_pred[g_csr[idx]];
            eq += (ps == pd);
            atomicAdd(&hist[w][ps], 1);
        }
        __syncwarp();
        #pragma unroll
        for (int off = 16; off; off >>= 1) eq += __shfl_down_sync(0xffffffffu, eq, off);
        float inv = g_invdeg[n];
        float p0 = fmaxf((float)hist[w][lane] * inv, 1e-5f);
        float p1 = fmaxf((float)hist[w][lane + 32] * inv, 1e-5f);
        float ent = -(p0 * logf(p0) + p1 * logf(p1));
        #pragma unroll
        for (int off = 16; off; off >>= 1) ent += __shfl_down_sync(0xffffffffu, ent, off);
        if (lane == 0) {
            float f1 = (float)eq * inv;
            g_f1[n] = f1; g_f2[n] = ent;
            red[w] = make_float4(f1, f1 * f1, ent, ent * ent);
        }
        __syncthreads();
        if (tid < 4) {
            float s = 0.0f;
            #pragma unroll
            for (int ww = 0; ww < 8; ww++) s += ((const float*)&red[ww])[tid];
            g_partials[bs * 4 + tid] = s;
        }
    }
}

// single-block: LN finalize over partials, then precompute per-node gate z
__global__ void k_lngate(const float* __restrict__ tau1, const float* __restrict__ tau2) {
    __shared__ float4 red4[1024];
    __shared__ float4 s_stat;
    int tid = threadIdx.x;
    float s0 = 0, s1 = 0, s2 = 0, s3 = 0;
    for (int bk = tid; bk < STATS_BLOCKS; bk += 1024) {
        s0 += g_partials[4 * bk + 0];
        s1 += g_partials[4 * bk + 1];
        s2 += g_partials[4 * bk + 2];
        s3 += g_partials[4 * bk + 3];
    }
    red4[tid] = make_float4(s0, s1, s2, s3);
    __syncthreads();
    for (int off = 512; off; off >>= 1) {
        if (tid < off) {
            red4[tid].x += red4[tid + off].x;
            red4[tid].y += red4[tid + off].y;
            red4[tid].z += red4[tid + off].z;
            red4[tid].w += red4[tid + off].w;
        }
        __syncthreads();
    }
    if (tid == 0) {
        const float invN = 1.0f / (float)NN;
        float m1 = red4[0].x * invN;
        float v1 = red4[0].y * invN - m1 * m1;
        float m2 = red4[0].z * invN;
        float v2 = red4[0].w * invN - m2 * m2;
        s_stat = make_float4(m1, rsqrtf(v1 + 1e-5f), m2, rsqrtf(v2 + 1e-5f));
    }
    __syncthreads();
    float m1 = s_stat.x, r1 = s_stat.y, m2 = s_stat.z, r2 = s_stat.w;
    float t1 = tau1[0], t2 = tau2[0];
    for (int n = tid; n < NN; n += 1024) {
        float z1 = 1.0f / (1.0f + expf((g_f1[n] - m1) * r1 - t1));
        float z2 = 1.0f / (1.0f + expf((g_f2[n] - m2) * r2 - t2));
        g_z[n] = z1 * z2;
    }
}

// iterations 1..9: combine (feat(i) = z*nm^2*agg + nm*own, written in-place
// over agg) FUSED with the FFMA2 GEMM + argmax on the fresh feat(i).
// cur = i&1: feat(i)/agg in (cur? B : A); own = feat(i-1) in (cur? A : B).
#define WTP 130
__global__ void __launch_bounds__(128) k_gemm_combine(int cur, const float* __restrict__ w,
                                                      const float* __restrict__ b) {
    __shared__ __align__(8) float ws_t[CC][WTP];
    __shared__ __align__(16) float4 srow[4][8][HH / 4];
    const float* __restrict__ Fown = cur ? g_featA : g_featB;
    float* __restrict__ Fio = cur ? g_featB : g_featA;   // agg in, feat(i) out
    int tid = threadIdx.x;

    for (int i = tid; i < HH * CC / 4; i += 128) {
        float4 v = ((const float4*)w)[i];
        int k = i >> 4;
        int c = (i & 15) * 4;
        ws_t[c + 0][k] = v.x; ws_t[c + 1][k] = v.y;
        ws_t[c + 2][k] = v.z; ws_t[c + 3][k] = v.w;
    }
    __syncthreads();

    int wp = tid >> 5, lane = tid & 31;
    int base = blockIdx.x * 32 + wp * 8;

    // combine 8 rows: r = z*nm^2*agg + nm*own; write back; stage in smem
    float4 tmp[8];
    #pragma unroll
    for (int r = 0; r < 8; r++) {
        int n = base + r;
        float nm = g_norm[n];
        float s_agg = g_z[n] * nm * nm;
        float4 ag = __ldg((const float4*)(Fio + (size_t)n * HH) + lane);
        float4 ow = __ldg((const float4*)(Fown + (size_t)n * HH) + lane);
        float4 o;
        o.x = s_agg * ag.x + nm * ow.x;
        o.y = s_agg * ag.y + nm * ow.y;
        o.z = s_agg * ag.z + nm * ow.z;
        o.w = s_agg * ag.w + nm * ow.w;
        ((float4*)(Fio + (size_t)n * HH))[lane] = o;
        tmp[r] = o;
    }
    #pragma unroll
    for (int r = 0; r < 8; r++)
        srow[wp][r][lane] = tmp[r];
    __syncwarp();

    u64 acc0[8], acc1[8];
    #pragma unroll
    for (int r = 0; r < 8; r++) { acc0[r] = 0ull; acc1[r] = 0ull; }

    const u64* w0p = (const u64*)&ws_t[lane][0];
    const u64* w1p = (const u64*)&ws_t[lane + 32][0];
    const float4* fr = &srow[wp][0][0];

    #pragma unroll 4
    for (int k4 = 0; k4 < HH / 4; k4++) {
        u64 wa0 = w0p[2 * k4], wa1 = w0p[2 * k4 + 1];
        u64 wb0 = w1p[2 * k4], wb1 = w1p[2 * k4 + 1];
        #pragma unroll
        for (int r = 0; r < 8; r++) {
            float4 f = fr[r * (HH / 4) + k4];
            u64 fp0 = pk(f.x, f.y);
            u64 fp1 = pk(f.z, f.w);
            acc0[r] = ffma2(fp0, wa0, acc0[r]);
            acc0[r] = ffma2(fp1, wa1, acc0[r]);
            acc1[r] = ffma2(fp0, wb0, acc1[r]);
            acc1[r] = ffma2(fp1, wb1, acc1[r]);
        }
    }

    float bias0 = b[lane], bias1 = b[lane + 32];
    #pragma unroll
    for (int r = 0; r < 8; r++) {
        float2 a0 = upk(acc0[r]);
        float2 a1 = upk(acc1[r]);
        float l0 = (a0.x + a0.y) + bias0;
        float l1 = (a1.x + a1.y) + bias1;
        float bv; int bc;
        if (l1 > l0) { bv = l1; bc = lane + 32; } else { bv = l0; bc = lane; }
        #pragma unroll
        for (int off = 16; off; off >>= 1) {
            float ov = __shfl_down_sync(0xffffffffu, bv, off);
            int   oc = __shfl_down_sync(0xffffffffu, bc, off);
            if (ov > bv || (ov == bv && oc < bc)) { bv = ov; bc = oc; }
        }
        if (lane == 0) g_pred[base + r] = bc;
    }
}

// final combine (iteration K-1): out = z*nm*agg + own -> dout
__global__ void k_combine_out(float* __restrict__ dout) {
    int i = blockIdx.x * blockDim.x + threadIdx.x;
    if (i >= NN * (HH / 4)) return;
    int n = i >> 5;
    // feat(9) in B (9 odd), agg9 in A
    float nm = g_norm[n];
    float s_agg = g_z[n] * nm;
    float4 ag = ((const float4*)g_featA)[i];
    float4 ow = ((const float4*)g_featB)[i];
    float4 o;
    o.x = s_agg * ag.x + ow.x;
    o.y = s_agg * ag.y + ow.y;
    o.z = s_agg * ag.z + ow.z;
    o.w = s_agg * ag.w + ow.w;
    ((float4*)dout)[i] = o;
}

// ---------------- host launcher ----------------
extern "C" void kernel_launch(void* const* d_in, const int* in_sizes, int n_in,
                              void* d_out, int out_size) {
    const float* feat   = (const float*)d_in[0];
    const float* logits = (const float*)d_in[1];
    const float* w_y    = (const float*)d_in[2];
    const float* b_y    = (const float*)d_in[3];
    const float* tau1   = (const float*)d_in[4];
    const float* tau2   = (const float*)d_in[5];
    const int*   src    = (const int*)d_in[6];
    const int*   dst    = (const int*)d_in[7];
    float* out = (float*)d_out;
    (void)in_sizes; (void)n_in; (void)out_size;

    const int NB1 = (NN + 1023) / 1024;

    k_zero<<<(NN + 255) / 256, 256>>>();
    k_deg<<<(EE + 255) / 256, 256>>>(dst);
    k_norm<<<(NN + 255) / 256, 256>>>();
    k_scan1<<<NB1, 1024>>>();
    k_scan2<<<1, 1>>>(NB1);
    k_scan3<<<(NN + 255) / 256, 256>>>();
    k_csrfill<<<(EE + 255) / 256, 256>>>(src, dst);
    k_init<<<(NN * (HH / 4) + 255) / 256, 256>>>(feat);

    const int warp_blocks = (NN * 32 + 255) / 256;
    for (int i = 0; i < KK; i++) {
        int cur = i & 1;
        if (i == 0) {
            k_argmax0<<<warp_blocks, 256>>>(logits);
        } else {
            k_gemm_combine<<<NN / 32, 128>>>(cur, w_y, b_y);
        }
        k_statsgather<<<GATHER_BLOCKS + STATS_BLOCKS, 256>>>(cur);
        k_lngate<<<1, 1024>>>(tau1, tau2);
    }
    k_combine_out<<<(NN * (HH / 4) + 255) / 256, 256>>>(out);
}

// round 9
// speedup vs baseline: 1.3484x; 1.3484x over previous
#include <cuda_runtime.h>
#include <math.h>

#define NN 100000
#define EE 1600000
#define HH 128
#define CC 64
#define KK 10

typedef unsigned long long u64;

// ---------------- device scratch (allocation-free workaround) ----------------
__device__ __align__(16) float g_featA[NN * HH];
__device__ __align__(16) float g_featB[NN * HH];
__device__ int   g_deg[NN];
__device__ float g_norm[NN];
__device__ float g_invdeg[NN];
__device__ int   g_scan[NN];
__device__ int   g_bsum[128];
__device__ int   g_rowstart[NN + 1];
__device__ int   g_rowcur[NN];
__device__ int   g_csr[EE];
__device__ int   g_pred[NN];
__device__ float g_f1[NN];
__device__ float g_f2[NN];
__device__ float g_partials[(NN / 32) * 4];
__device__ float g_ln[4];   // mean1, rstd1, mean2, rstd2
__device__ unsigned int g_ctr;

// ---------------- packed fp32x2 helpers ----------------
__device__ __forceinline__ u64 ffma2(u64 a, u64 b, u64 c) {
    u64 d;
    asm("fma.rn.f32x2 %0, %1, %2, %3;" : "=l"(d) : "l"(a), "l"(b), "l"(c));
    return d;
}
__device__ __forceinline__ u64 pk(float x, float y) {
    u64 d;
    asm("mov.b64 %0, {%1, %2};" : "=l"(d) : "f"(x), "f"(y));
    return d;
}
__device__ __forceinline__ float2 upk(u64 v) {
    float2 r;
    asm("mov.b64 {%0, %1}, %2;" : "=f"(r.x), "=f"(r.y) : "l"(v));
    return r;
}

// ---------------- setup kernels ----------------
__global__ void k_zero() {
    int i = blockIdx.x * blockDim.x + threadIdx.x;
    if (i < NN) { g_deg[i] = 0; g_rowcur[i] = 0; }
    if (i == 0) g_ctr = 0u;
}

__global__ void k_deg(const int* __restrict__ dst) {
    int e = blockIdx.x * blockDim.x + threadIdx.x;
    if (e < EE) atomicAdd(&g_deg[dst[e]], 1);
}

__global__ void k_norm() {
    int i = blockIdx.x * blockDim.x + threadIdx.x;
    if (i < NN) {
        int d = g_deg[i];
        float dc = (d > 0) ? (float)d : 1.0f;
        g_norm[i] = rsqrtf(dc);
        g_invdeg[i] = 1.0f / dc;
    }
}

// inclusive scan within 1024-element blocks
__global__ void k_scan1() {
    __shared__ int sh[1024];
    int tid = threadIdx.x;
    int i = blockIdx.x * 1024 + tid;
    int v = (i < NN) ? g_deg[i] : 0;
    sh[tid] = v;
    __syncthreads();
    for (int off = 1; off < 1024; off <<= 1) {
        int t = (tid >= off) ? sh[tid - off] : 0;
        __syncthreads();
        sh[tid] += t;
        __syncthreads();
    }
    if (i < NN) g_scan[i] = sh[tid];
    if (tid == 1023) g_bsum[blockIdx.x] = sh[1023];
}

__global__ void k_scan2(int nb) {
    int run = 0;
    for (int b = 0; b < nb; b++) { int t = g_bsum[b]; g_bsum[b] = run; run += t; }
}

__global__ void k_scan3() {
    int i = blockIdx.x * blockDim.x + threadIdx.x;
    if (i < NN) g_rowstart[i] = g_scan[i] - g_deg[i] + g_bsum[i >> 10];
    if (i == 0) g_rowstart[NN] = EE;
}

__global__ void k_csrfill(const int* __restrict__ src, const int* __restrict__ dst) {
    int e = blockIdx.x * blockDim.x + threadIdx.x;
    if (e < EE) {
        int d = dst[e];
        int pos = g_rowstart[d] + atomicAdd(&g_rowcur[d], 1);
        g_csr[pos] = src[e];
    }
}

// feat buffer initialized to pre-scaled feat: Fs(0) = feat_in * norm
__global__ void k_init(const float* __restrict__ fin) {
    int i = blockIdx.x * blockDim.x + threadIdx.x;
    if (i < NN * (HH / 4)) {
        int n = i >> 5;
        float nm = g_norm[n];
        float4 v = ((const float4*)fin)[i];
        v.x *= nm; v.y *= nm; v.z *= nm; v.w *= nm;
        ((float4*)g_featA)[i] = v;
    }
}

// ---------------- per-iteration kernels ----------------

// iteration 0: argmax over the input logits
__global__ void k_argmax0(const float* __restrict__ logits) {
    int n = (blockIdx.x * blockDim.x + threadIdx.x) >> 5;
    int lane = threadIdx.x & 31;
    if (n >= NN) return;
    const float* row = logits + (size_t)n * CC;
    float v0 = row[lane], v1 = row[lane + 32];
    float bv; int bc;
    if (v1 > v0) { bv = v1; bc = lane + 32; } else { bv = v0; bc = lane; }
    #pragma unroll
    for (int off = 16; off; off >>= 1) {
        float ov = __shfl_down_sync(0xffffffffu, bv, off);
        int   oc = __shfl_down_sync(0xffffffffu, bc, off);
        if (ov > bv || (ov == bv && oc < bc)) { bv = ov; bc = oc; }
    }
    if (lane == 0) g_pred[n] = bc;
}

// iterations 1..: fused GEMM (scaled feat @ w_y + b_y) + row argmax.
// K-packed FFMA2 (proven round-7 version).
#define WTP 130
__global__ void __launch_bounds__(128) k_gemm_argmax(int sbuf, const float* __restrict__ w,
                                                     const float* __restrict__ b) {
    __shared__ __align__(8) float ws_t[CC][WTP];
    __shared__ __align__(16) float4 srow[4][8][HH / 4];
    const float* __restrict__ F = sbuf ? g_featB : g_featA;
    int tid = threadIdx.x;

    for (int i = tid; i < HH * CC / 4; i += 128) {
        float4 v = ((const float4*)w)[i];
        int k = i >> 4;
        int c = (i & 15) * 4;
        ws_t[c + 0][k] = v.x; ws_t[c + 1][k] = v.y;
        ws_t[c + 2][k] = v.z; ws_t[c + 3][k] = v.w;
    }
    __syncthreads();

    int wp = tid >> 5, lane = tid & 31;
    int base = blockIdx.x * 32 + wp * 8;

    float4 tmp[8];
    #pragma unroll
    for (int r = 0; r < 8; r++)
        tmp[r] = __ldg((const float4*)(F + (size_t)(base + r) * HH) + lane);
    #pragma unroll
    for (int r = 0; r < 8; r++)
        srow[wp][r][lane] = tmp[r];
    __syncwarp();

    u64 acc0[8], acc1[8];
    #pragma unroll
    for (int r = 0; r < 8; r++) { acc0[r] = 0ull; acc1[r] = 0ull; }

    const u64* w0p = (const u64*)&ws_t[lane][0];
    const u64* w1p = (const u64*)&ws_t[lane + 32][0];
    const float4* fr = &srow[wp][0][0];

    #pragma unroll 4
    for (int k4 = 0; k4 < HH / 4; k4++) {
        u64 wa0 = w0p[2 * k4], wa1 = w0p[2 * k4 + 1];
        u64 wb0 = w1p[2 * k4], wb1 = w1p[2 * k4 + 1];
        #pragma unroll
        for (int r = 0; r < 8; r++) {
            float4 f = fr[r * (HH / 4) + k4];
            u64 fp0 = pk(f.x, f.y);
            u64 fp1 = pk(f.z, f.w);
            acc0[r] = ffma2(fp0, wa0, acc0[r]);
            acc0[r] = ffma2(fp1, wa1, acc0[r]);
            acc1[r] = ffma2(fp0, wb0, acc1[r]);
            acc1[r] = ffma2(fp1, wb1, acc1[r]);
        }
    }

    float bias0 = b[lane], bias1 = b[lane + 32];
    #pragma unroll
    for (int r = 0; r < 8; r++) {
        float2 a0 = upk(acc0[r]);
        float2 a1 = upk(acc1[r]);
        float l0 = (a0.x + a0.y) + bias0;
        float l1 = (a1.x + a1.y) + bias1;
        float bv; int bc;
        if (l1 > l0) { bv = l1; bc = lane + 32; } else { bv = l0; bc = lane; }
        #pragma unroll
        for (int off = 16; off; off >>= 1) {
            float ov = __shfl_down_sync(0xffffffffu, bv, off);
            int   oc = __shfl_down_sync(0xffffffffu, bc, off);
            if (ov > bv || (ov == bv && oc < bc)) { bv = ov; bc = oc; }
        }
        if (lane == 0) g_pred[base + r] = bc;
    }
}

// fused neighborhood stats (round-7 math, unchanged) + last-block LN finalize.
__global__ void k_stats() {
    __shared__ int hist[32][CC];
    __shared__ float4 red[32];
    __shared__ bool s_last;
    int tid = threadIdx.x, w = tid >> 5, lane = tid & 31;
    int n = blockIdx.x * 32 + w;
    hist[w][lane] = 0; hist[w][lane + 32] = 0;
    __syncwarp();
    int pd = g_pred[n];
    int rs = g_rowstart[n], re = g_rowstart[n + 1];
    int eq = 0;
    for (int idx = rs + lane; idx < re; idx += 32) {
        int ps = g_pred[g_csr[idx]];
        eq += (ps == pd);
        atomicAdd(&hist[w][ps], 1);
    }
    __syncwarp();
    #pragma unroll
    for (int off = 16; off; off >>= 1) eq += __shfl_down_sync(0xffffffffu, eq, off);
    float inv = g_invdeg[n];
    float p0 = fmaxf((float)hist[w][lane] * inv, 1e-5f);
    float p1 = fmaxf((float)hist[w][lane + 32] * inv, 1e-5f);
    float ent = -(p0 * logf(p0) + p1 * logf(p1));
    #pragma unroll
    for (int off = 16; off; off >>= 1) ent += __shfl_down_sync(0xffffffffu, ent, off);
    if (lane == 0) {
        float f1 = (float)eq * inv;
        g_f1[n] = f1; g_f2[n] = ent;
        red[w] = make_float4(f1, f1 * f1, ent, ent * ent);
    }
    __syncthreads();
    if (tid < 4) {
        float s = 0.0f;
        #pragma unroll
        for (int ww = 0; ww < 32; ww++) s += ((const float*)&red[ww])[tid];
        g_partials[blockIdx.x * 4 + tid] = s;
    }

    // ---- last-block LayerNorm finalize (replaces separate k_ln launch) ----
    __threadfence();
    if (tid == 0) {
        unsigned int prev = atomicInc(&g_ctr, gridDim.x - 1);  // self-wrapping
        s_last = (prev == gridDim.x - 1);
    }
    __syncthreads();
    if (!s_last) return;

    __shared__ float4 red4[1024];
    float s0 = 0, s1 = 0, s2 = 0, s3 = 0;
    for (int bk = tid; bk < NN / 32; bk += 1024) {
        s0 += g_partials[4 * bk + 0];
        s1 += g_partials[4 * bk + 1];
        s2 += g_partials[4 * bk + 2];
        s3 += g_partials[4 * bk + 3];
    }
    red4[tid] = make_float4(s0, s1, s2, s3);
    __syncthreads();
    for (int off = 512; off; off >>= 1) {
        if (tid < off) {
            red4[tid].x += red4[tid + off].x;
            red4[tid].y += red4[tid + off].y;
            red4[tid].z += red4[tid + off].z;
            red4[tid].w += red4[tid + off].w;
        }
        __syncthreads();
    }
    if (tid == 0) {
        const float invN = 1.0f / (float)NN;
        float m1 = red4[0].x * invN;
        float v1 = red4[0].y * invN - m1 * m1;
        float m2 = red4[0].z * invN;
        float v2 = red4[0].w * invN - m2 * m2;
        g_ln[0] = m1; g_ln[1] = rsqrtf(v1 + 1e-5f);
        g_ln[2] = m2; g_ln[3] = rsqrtf(v2 + 1e-5f);
    }
}

// fused SpMM gather + gate + combine + (folded) next-iteration scale (fp32).
// 8-deep load batches for higher MLP.
__global__ void k_spmm(int sbuf, float* __restrict__ dout, int last,
                       const float* __restrict__ tau1, const float* __restrict__ tau2) {
    int n = (blockIdx.x * blockDim.x + threadIdx.x) >> 5;
    int lane = threadIdx.x & 31;
    if (n >= NN) return;
    const float* __restrict__ Fs = sbuf ? g_featB : g_featA;
    float* __restrict__ Fd = last ? dout : (sbuf ? g_featA : g_featB);

    int rs = g_rowstart[n], re = g_rowstart[n + 1];
    float4 acc = make_float4(0.f, 0.f, 0.f, 0.f);
    int idx = rs;
    for (; idx + 8 <= re; idx += 8) {
        int s[8];
        #pragma unroll
        for (int j = 0; j < 8; j++) s[j] = g_csr[idx + j];
        float4 v[8];
        #pragma unroll
        for (int j = 0; j < 8; j++)
            v[j] = __ldg((const float4*)(Fs + (size_t)s[j] * HH) + lane);
        acc.x += ((v[0].x + v[1].x) + (v[2].x + v[3].x)) + ((v[4].x + v[5].x) + (v[6].x + v[7].x));
        acc.y += ((v[0].y + v[1].y) + (v[2].y + v[3].y)) + ((v[4].y + v[5].y) + (v[6].y + v[7].y));
        acc.z += ((v[0].z + v[1].z) + (v[2].z + v[3].z)) + ((v[4].z + v[5].z) + (v[6].z + v[7].z));
        acc.w += ((v[0].w + v[1].w) + (v[2].w + v[3].w)) + ((v[4].w + v[5].w) + (v[6].w + v[7].w));
    }
    for (; idx + 4 <= re; idx += 4) {
        int s0 = g_csr[idx], s1 = g_csr[idx + 1], s2 = g_csr[idx + 2], s3 = g_csr[idx + 3];
        float4 v0 = __ldg((const float4*)(Fs + (size_t)s0 * HH) + lane);
        float4 v1 = __ldg((const float4*)(Fs + (size_t)s1 * HH) + lane);
        float4 v2 = __ldg((const float4*)(Fs + (size_t)s2 * HH) + lane);
        float4 v3 = __ldg((const float4*)(Fs + (size_t)s3 * HH) + lane);
        acc.x += (v0.x + v1.x) + (v2.x + v3.x);
        acc.y += (v0.y + v1.y) + (v2.y + v3.y);
        acc.z += (v0.z + v1.z) + (v2.z + v3.z);
        acc.w += (v0.w + v1.w) + (v2.w + v3.w);
    }
    for (; idx < re; idx++) {
        int s = g_csr[idx];
        float4 v = __ldg((const float4*)(Fs + (size_t)s * HH) + lane);
        acc.x += v.x; acc.y += v.y; acc.z += v.z; acc.w += v.w;
    }

    float m1 = g_ln[0], r1 = g_ln[1], m2 = g_ln[2], r2 = g_ln[3];
    float z1 = 1.0f / (1.0f + expf((g_f1[n] - m1) * r1 - tau1[0]));
    float z2 = 1.0f / (1.0f + expf((g_f2[n] - m2) * r2 - tau2[0]));
    float z = z1 * z2;
    float nm = g_norm[n];
    float s_agg = last ? (z * nm) : (z * nm * nm);
    float s_own = last ? 1.0f : nm;

    float4 own = ((const float4*)(Fs + (size_t)n * HH))[lane];
    float4 o;
    o.x = s_agg * acc.x + s_own * own.x;
    o.y = s_agg * acc.y + s_own * own.y;
    o.z = s_agg * acc.z + s_own * own.z;
    o.w = s_agg * acc.w + s_own * own.w;
    __stcs((float4*)(Fd + (size_t)n * HH) + lane, o);
}

// ---------------- host launcher ----------------
extern "C" void kernel_launch(void* const* d_in, const int* in_sizes, int n_in,
                              void* d_out, int out_size) {
    const float* feat   = (const float*)d_in[0];
    const float* logits = (const float*)d_in[1];
    const float* w_y    = (const float*)d_in[2];
    const float* b_y    = (const float*)d_in[3];
    const float* tau1   = (const float*)d_in[4];
    const float* tau2   = (const float*)d_in[5];
    const int*   src    = (const int*)d_in[6];
    const int*   dst    = (const int*)d_in[7];
    float* out = (float*)d_out;
    (void)in_sizes; (void)n_in; (void)out_size;

    const int NB1 = (NN + 1023) / 1024;

    k_zero<<<(NN + 255) / 256, 256>>>();
    k_deg<<<(EE + 255) / 256, 256>>>(dst);
    k_norm<<<(NN + 255) / 256, 256>>>();
    k_scan1<<<NB1, 1024>>>();
    k_scan2<<<1, 1>>>(NB1);
    k_scan3<<<(NN + 255) / 256, 256>>>();
    k_csrfill<<<(EE + 255) / 256, 256>>>(src, dst);
    k_init<<<(NN * (HH / 4) + 255) / 256, 256>>>(feat);

    const int warp_blocks = (NN * 32 + 255) / 256;
    for (int i = 0; i < KK; i++) {
        int sbuf = i & 1;
        if (i == 0) {
            k_argmax0<<<warp_blocks, 256>>>(logits);
        } else {
            k_gemm_argmax<<<NN / 32, 128>>>(sbuf, w_y, b_y);
        }
        k_stats<<<NN / 32, 1024>>>();
        k_spmm<<<warp_blocks, 256>>>(sbuf, out, (i == KK - 1) ? 1 : 0, tau1, tau2);
    }
}

// round 10
// speedup vs baseline: 1.4999x; 1.1124x over previous
#include <cuda_runtime.h>
#include <math.h>

#define NN 100000
#define EE 1600000
#define HH 128
#define CC 64
#define KK 10

typedef unsigned long long u64;

// ---------------- device scratch (allocation-free workaround) ----------------
__device__ __align__(16) float g_featA[NN * HH];
__device__ __align__(16) float g_featB[NN * HH];
__device__ int   g_deg[NN];
__device__ float g_norm[NN];
__device__ float g_invdeg[NN];
__device__ int   g_scan[NN];
__device__ int   g_bsum[128];
__device__ int   g_rowstart[NN + 1];
__device__ int   g_rowcur[NN];
__device__ int   g_csr[EE];
__device__ int   g_pred[NN];
__device__ float g_f1[NN];
__device__ float g_f2[NN];
__device__ float g_lnacc[4];   // atomic accumulators: S(f1), S(f1^2), S(f2), S(f2^2)

// ---------------- packed fp32x2 helpers ----------------
__device__ __forceinline__ u64 ffma2(u64 a, u64 b, u64 c) {
    u64 d;
    asm("fma.rn.f32x2 %0, %1, %2, %3;" : "=l"(d) : "l"(a), "l"(b), "l"(c));
    return d;
}
__device__ __forceinline__ u64 pk(float x, float y) {
    u64 d;
    asm("mov.b64 %0, {%1, %2};" : "=l"(d) : "f"(x), "f"(y));
    return d;
}
__device__ __forceinline__ float2 upk(u64 v) {
    float2 r;
    asm("mov.b64 {%0, %1}, %2;" : "=f"(r.x), "=f"(r.y) : "l"(v));
    return r;
}

// ---------------- setup kernels ----------------
__global__ void k_zero() {
    int i = blockIdx.x * blockDim.x + threadIdx.x;
    if (i < NN) { g_deg[i] = 0; g_rowcur[i] = 0; }
}

__global__ void k_deg(const int* __restrict__ dst) {
    int e = blockIdx.x * blockDim.x + threadIdx.x;
    if (e < EE) atomicAdd(&g_deg[dst[e]], 1);
}

__global__ void k_norm() {
    int i = blockIdx.x * blockDim.x + threadIdx.x;
    if (i < NN) {
        int d = g_deg[i];
        float dc = (d > 0) ? (float)d : 1.0f;
        g_norm[i] = rsqrtf(dc);
        g_invdeg[i] = 1.0f / dc;
    }
}

// inclusive scan within 1024-element blocks
__global__ void k_scan1() {
    __shared__ int sh[1024];
    int tid = threadIdx.x;
    int i = blockIdx.x * 1024 + tid;
    int v = (i < NN) ? g_deg[i] : 0;
    sh[tid] = v;
    __syncthreads();
    for (int off = 1; off < 1024; off <<= 1) {
        int t = (tid >= off) ? sh[tid - off] : 0;
        __syncthreads();
        sh[tid] += t;
        __syncthreads();
    }
    if (i < NN) g_scan[i] = sh[tid];
    if (tid == 1023) g_bsum[blockIdx.x] = sh[1023];
}

__global__ void k_scan2(int nb) {
    int run = 0;
    for (int b = 0; b < nb; b++) { int t = g_bsum[b]; g_bsum[b] = run; run += t; }
}

__global__ void k_scan3() {
    int i = blockIdx.x * blockDim.x + threadIdx.x;
    if (i < NN) g_rowstart[i] = g_scan[i] - g_deg[i] + g_bsum[i >> 10];
    if (i == 0) g_rowstart[NN] = EE;
}

__global__ void k_csrfill(const int* __restrict__ src, const int* __restrict__ dst) {
    int e = blockIdx.x * blockDim.x + threadIdx.x;
    if (e < EE) {
        int d = dst[e];
        int pos = g_rowstart[d] + atomicAdd(&g_rowcur[d], 1);
        g_csr[pos] = src[e];
    }
}

// feat buffer initialized to pre-scaled feat: Fs(0) = feat_in * norm
__global__ void k_init(const float* __restrict__ fin) {
    int i = blockIdx.x * blockDim.x + threadIdx.x;
    if (i < NN * (HH / 4)) {
        int n = i >> 5;
        float nm = g_norm[n];
        float4 v = ((const float4*)fin)[i];
        v.x *= nm; v.y *= nm; v.z *= nm; v.w *= nm;
        ((float4*)g_featA)[i] = v;
    }
}

// ---------------- per-iteration kernels ----------------

// iteration 0: argmax over the input logits (also zeroes LN accumulators)
__global__ void k_argmax0(const float* __restrict__ logits) {
    if (blockIdx.x == 0 && threadIdx.x < 4) g_lnacc[threadIdx.x] = 0.0f;
    int n = (blockIdx.x * blockDim.x + threadIdx.x) >> 5;
    int lane = threadIdx.x & 31;
    if (n >= NN) return;
    const float* row = logits + (size_t)n * CC;
    float v0 = row[lane], v1 = row[lane + 32];
    float bv; int bc;
    if (v1 > v0) { bv = v1; bc = lane + 32; } else { bv = v0; bc = lane; }
    #pragma unroll
    for (int off = 16; off; off >>= 1) {
        float ov = __shfl_down_sync(0xffffffffu, bv, off);
        int   oc = __shfl_down_sync(0xffffffffu, bc, off);
        if (ov > bv || (ov == bv && oc < bc)) { bv = ov; bc = oc; }
    }
    if (lane == 0) g_pred[n] = bc;
}

// iterations 1..: fused GEMM (scaled feat @ w_y + b_y) + row argmax.
// K-packed FFMA2 (proven round-7 version). Block 0 zeroes LN accumulators
// for the k_stats that follows this kernel in the same iteration.
#define WTP 130
__global__ void __launch_bounds__(128) k_gemm_argmax(int sbuf, const float* __restrict__ w,
                                                     const float* __restrict__ b) {
    __shared__ __align__(8) float ws_t[CC][WTP];
    __shared__ __align__(16) float4 srow[4][8][HH / 4];
    const float* __restrict__ F = sbuf ? g_featB : g_featA;
    int tid = threadIdx.x;
    if (blockIdx.x == 0 && tid < 4) g_lnacc[tid] = 0.0f;

    for (int i = tid; i < HH * CC / 4; i += 128) {
        float4 v = ((const float4*)w)[i];
        int k = i >> 4;
        int c = (i & 15) * 4;
        ws_t[c + 0][k] = v.x; ws_t[c + 1][k] = v.y;
        ws_t[c + 2][k] = v.z; ws_t[c + 3][k] = v.w;
    }
    __syncthreads();

    int wp = tid >> 5, lane = tid & 31;
    int base = blockIdx.x * 32 + wp * 8;

    float4 tmp[8];
    #pragma unroll
    for (int r = 0; r < 8; r++)
        tmp[r] = __ldg((const float4*)(F + (size_t)(base + r) * HH) + lane);
    #pragma unroll
    for (int r = 0; r < 8; r++)
        srow[wp][r][lane] = tmp[r];
    __syncwarp();

    u64 acc0[8], acc1[8];
    #pragma unroll
    for (int r = 0; r < 8; r++) { acc0[r] = 0ull; acc1[r] = 0ull; }

    const u64* w0p = (const u64*)&ws_t[lane][0];
    const u64* w1p = (const u64*)&ws_t[lane + 32][0];
    const float4* fr = &srow[wp][0][0];

    #pragma unroll 4
    for (int k4 = 0; k4 < HH / 4; k4++) {
        u64 wa0 = w0p[2 * k4], wa1 = w0p[2 * k4 + 1];
        u64 wb0 = w1p[2 * k4], wb1 = w1p[2 * k4 + 1];
        #pragma unroll
        for (int r = 0; r < 8; r++) {
            float4 f = fr[r * (HH / 4) + k4];
            u64 fp0 = pk(f.x, f.y);
            u64 fp1 = pk(f.z, f.w);
            acc0[r] = ffma2(fp0, wa0, acc0[r]);
            acc0[r] = ffma2(fp1, wa1, acc0[r]);
            acc1[r] = ffma2(fp0, wb0, acc1[r]);
            acc1[r] = ffma2(fp1, wb1, acc1[r]);
        }
    }

    float bias0 = b[lane], bias1 = b[lane + 32];
    #pragma unroll
    for (int r = 0; r < 8; r++) {
        float2 a0 = upk(acc0[r]);
        float2 a1 = upk(acc1[r]);
        float l0 = (a0.x + a0.y) + bias0;
        float l1 = (a1.x + a1.y) + bias1;
        float bv; int bc;
        if (l1 > l0) { bv = l1; bc = lane + 32; } else { bv = l0; bc = lane; }
        #pragma unroll
        for (int off = 16; off; off >>= 1) {
            float ov = __shfl_down_sync(0xffffffffu, bv, off);
            int   oc = __shfl_down_sync(0xffffffffu, bc, off);
            if (ov > bv || (ov == bv && oc < bc)) { bv = ov; bc = oc; }
        }
        if (lane == 0) g_pred[base + r] = bc;
    }
}

// fused neighborhood stats: f1 (agreement) + f2 (entropy of class histogram).
// Per-block LN partials go straight into global atomic accumulators (RED.F32,
// no fence, no tail block). 1024 threads = 32 nodes/block.
__global__ void k_stats() {
    __shared__ int hist[32][CC];
    __shared__ float4 red[32];
    int tid = threadIdx.x, w = tid >> 5, lane = tid & 31;
    int n = blockIdx.x * 32 + w;
    hist[w][lane] = 0; hist[w][lane + 32] = 0;
    __syncwarp();
    int pd = g_pred[n];
    int rs = g_rowstart[n], re = g_rowstart[n + 1];
    int eq = 0;
    for (int idx = rs + lane; idx < re; idx += 32) {
        int ps = g_pred[g_csr[idx]];
        eq += (ps == pd);
        atomicAdd(&hist[w][ps], 1);
    }
    __syncwarp();
    #pragma unroll
    for (int off = 16; off; off >>= 1) eq += __shfl_down_sync(0xffffffffu, eq, off);
    float inv = g_invdeg[n];
    float p0 = fmaxf((float)hist[w][lane] * inv, 1e-5f);
    float p1 = fmaxf((float)hist[w][lane + 32] * inv, 1e-5f);
    float ent = -(p0 * logf(p0) + p1 * logf(p1));
    #pragma unroll
    for (int off = 16; off; off >>= 1) ent += __shfl_down_sync(0xffffffffu, ent, off);
    if (lane == 0) {
        float f1 = (float)eq * inv;
        g_f1[n] = f1; g_f2[n] = ent;
        red[w] = make_float4(f1, f1 * f1, ent, ent * ent);
    }
    __syncthreads();
    if (tid < 4) {
        float s = 0.0f;
        #pragma unroll
        for (int ww = 0; ww < 32; ww++) s += ((const float*)&red[ww])[tid];
        atomicAdd(&g_lnacc[tid], s);
    }
}

// fused SpMM gather + gate + combine + (folded) next-iteration scale (fp32).
// LayerNorm mean/rstd finalized inline from the 4 atomic accumulators.
__global__ void k_spmm(int sbuf, float* __restrict__ dout, int last,
                       const float* __restrict__ tau1, const float* __restrict__ tau2) {
    int n = (blockIdx.x * blockDim.x + threadIdx.x) >> 5;
    int lane = threadIdx.x & 31;
    if (n >= NN) return;
    const float* __restrict__ Fs = sbuf ? g_featB : g_featA;
    float* __restrict__ Fd = last ? dout : (sbuf ? g_featA : g_featB);

    int rs = g_rowstart[n], re = g_rowstart[n + 1];
    float4 own = ((const float4*)(Fs + (size_t)n * HH))[lane];
    float4 acc = make_float4(0.f, 0.f, 0.f, 0.f);
    int idx = rs;
    for (; idx + 4 <= re; idx += 4) {
        int s0 = g_csr[idx], s1 = g_csr[idx + 1], s2 = g_csr[idx + 2], s3 = g_csr[idx + 3];
        float4 v0 = __ldg((const float4*)(Fs + (size_t)s0 * HH) + lane);
        float4 v1 = __ldg((const float4*)(Fs + (size_t)s1 * HH) + lane);
        float4 v2 = __ldg((const float4*)(Fs + (size_t)s2 * HH) + lane);
        float4 v3 = __ldg((const float4*)(Fs + (size_t)s3 * HH) + lane);
        acc.x += (v0.x + v1.x) + (v2.x + v3.x);
        acc.y += (v0.y + v1.y) + (v2.y + v3.y);
        acc.z += (v0.z + v1.z) + (v2.z + v3.z);
        acc.w += (v0.w + v1.w) + (v2.w + v3.w);
    }
    for (; idx < re; idx++) {
        int s = g_csr[idx];
        float4 v = __ldg((const float4*)(Fs + (size_t)s * HH) + lane);
        acc.x += v.x; acc.y += v.y; acc.z += v.z; acc.w += v.w;
    }

    // inline LN finalize from atomic sums (cheap: few flops + 2 rsqrt per thread)
    const float invN = 1.0f / (float)NN;
    float m1 = g_lnacc[0] * invN;
    float v1 = g_lnacc[1] * invN - m1 * m1;
    float m2 = g_lnacc[2] * invN;
    float v2 = g_lnacc[3] * invN - m2 * m2;
    float r1 = rsqrtf(v1 + 1e-5f);
    float r2 = rsqrtf(v2 + 1e-5f);

    float z1 = 1.0f / (1.0f + expf((g_f1[n] - m1) * r1 - tau1[0]));
    float z2 = 1.0f / (1.0f + expf((g_f2[n] - m2) * r2 - tau2[0]));
    float z = z1 * z2;
    float nm = g_norm[n];
    float s_agg = last ? (z * nm) : (z * nm * nm);
    float s_own = last ? 1.0f : nm;

    float4 o;
    o.x = s_agg * acc.x + s_own * own.x;
    o.y = s_agg * acc.y + s_own * own.y;
    o.z = s_agg * acc.z + s_own * own.z;
    o.w = s_agg * acc.w + s_own * own.w;
    __stcs((float4*)(Fd + (size_t)n * HH) + lane, o);
}

// ---------------- host launcher ----------------
extern "C" void kernel_launch(void* const* d_in, const int* in_sizes, int n_in,
                              void* d_out, int out_size) {
    const float* feat   = (const float*)d_in[0];
    const float* logits = (const float*)d_in[1];
    const float* w_y    = (const float*)d_in[2];
    const float* b_y    = (const float*)d_in[3];
    const float* tau1   = (const float*)d_in[4];
    const float* tau2   = (const float*)d_in[5];
    const int*   src    = (const int*)d_in[6];
    const int*   dst    = (const int*)d_in[7];
    float* out = (float*)d_out;
    (void)in_sizes; (void)n_in; (void)out_size;

    const int NB1 = (NN + 1023) / 1024;

    k_zero<<<(NN + 255) / 256, 256>>>();
    k_deg<<<(EE + 255) / 256, 256>>>(dst);
    k_norm<<<(NN + 255) / 256, 256>>>();
    k_scan1<<<NB1, 1024>>>();
    k_scan2<<<1, 1>>>(NB1);
    k_scan3<<<(NN + 255) / 256, 256>>>();
    k_csrfill<<<(EE + 255) / 256, 256>>>(src, dst);
    k_init<<<(NN * (HH / 4) + 255) / 256, 256>>>(feat);

    const int warp_blocks = (NN * 32 + 255) / 256;
    for (int i = 0; i < KK; i++) {
        int sbuf = i & 1;
        if (i == 0) {
            k_argmax0<<<warp_blocks, 256>>>(logits);
        } else {
            k_gemm_argmax<<<NN / 32, 128>>>(sbuf, w_y, b_y);
        }
        k_stats<<<NN / 32, 1024>>>();
        k_spmm<<<warp_blocks, 256>>>(sbuf, out, (i == KK - 1) ? 1 : 0, tau1, tau2);
    }
}